// round 11
// baseline (speedup 1.0000x reference)
#include <cuda_runtime.h>
#include <cstdint>

// ExpectationSoftmaxLayer: s[b,o] = sum_i p*z, p = softmax(tau*z, i),
// z[b,o,i] = x[b,i] * leaky_clamp(w[o,i], 0, 1, 0.1)
//
// Round-10 strategy (MUFU/FMA pipe balancing):
//   arg = x * awk  (awk = leaky_clamp(w)*tau*log2e, precomputed)
//   e   = 2^arg    -- computed on MUFU (ex2.approx.f32) for ~11/16 of the
//                     work and on the FMA pipe (deg-7 Taylor, packed f32x2
//                     FFMA2) for ~5/16, balancing the two pipes.
//   s   = (sum arg*e)/(sum e)/k
// All muls/adds/fmas use packed f32x2 (Blackwell FFMA2) => half fma-pipe cost.

#define B_    256
#define IN_   1024
#define OUT_  1024

#define RB_B  4
#define RB_O  2
#define WARPS 8

#define LOG2E 1.4426950408889634f

__device__ float g_awk[OUT_ * IN_];

// ---------- packed f32x2 helpers (sm_103a FFMA2 path) ----------
__device__ __forceinline__ uint64_t pk2(float lo, float hi) {
    uint64_t r;
    asm("mov.b64 %0, {%1, %2};" : "=l"(r) : "f"(lo), "f"(hi));
    return r;
}
__device__ __forceinline__ void unpk2(uint64_t v, float& lo, float& hi) {
    asm("mov.b64 {%0, %1}, %2;" : "=f"(lo), "=f"(hi) : "l"(v));
}
__device__ __forceinline__ uint64_t mul2(uint64_t a, uint64_t b) {
    uint64_t d;
    asm("mul.rn.f32x2 %0, %1, %2;" : "=l"(d) : "l"(a), "l"(b));
    return d;
}
__device__ __forceinline__ uint64_t add2(uint64_t a, uint64_t b) {
    uint64_t d;
    asm("add.rn.f32x2 %0, %1, %2;" : "=l"(d) : "l"(a), "l"(b));
    return d;
}
__device__ __forceinline__ uint64_t fma2(uint64_t a, uint64_t b, uint64_t c) {
    uint64_t d;
    asm("fma.rn.f32x2 %0, %1, %2, %3;" : "=l"(d) : "l"(a), "l"(b), "l"(c));
    return d;
}
__device__ __forceinline__ uint64_t dup2(float f) {
    uint32_t b = __float_as_uint(f);
    return (uint64_t)b | ((uint64_t)b << 32);
}

__device__ __forceinline__ float ex2f(float a) {
    float r;
    asm("ex2.approx.ftz.f32 %0, %1;" : "=f"(r) : "f"(a));
    return r;
}

// 2^a via MUFU on both packed halves
__device__ __forceinline__ uint64_t exp2_mufu2(uint64_t a) {
    float lo, hi;
    unpk2(a, lo, hi);
    return pk2(ex2f(lo), ex2f(hi));
}

// 2^a via degree-7 Taylor (coeffs ln2^k/k!), packed FFMA2.
// Valid to ~2e-6 rel for |a| <= ~1.3; args here are bounded ~1.1.
__device__ __forceinline__ uint64_t exp2_poly2(uint64_t a) {
    uint64_t r = fma2(dup2(1.5252734e-5f), a, dup2(1.5403530e-4f));
    r = fma2(r, a, dup2(1.3333558e-3f));
    r = fma2(r, a, dup2(9.6181291e-3f));
    r = fma2(r, a, dup2(5.5504109e-2f));
    r = fma2(r, a, dup2(2.4022651e-1f));
    r = fma2(r, a, dup2(6.9314718e-1f));
    r = fma2(r, a, dup2(1.0f));
    return r;
}

// leaky_clamp(x, 0, 1, 0.1) == 0.1*x + 0.9*saturate(x)
__device__ __forceinline__ float leaky_clamp01(float v) {
    return fmaf(0.9f, __saturatef(v), 0.1f * v);
}

__global__ __launch_bounds__(256)
void prep_awk_kernel(const float* __restrict__ w,
                     const float* __restrict__ log_tau) {
    const float k = expf(log_tau[0]) * LOG2E;
    int idx = (blockIdx.x * blockDim.x + threadIdx.x) * 4;
    float4 v = *reinterpret_cast<const float4*>(w + idx);
    float4 o;
    o.x = leaky_clamp01(v.x) * k;
    o.y = leaky_clamp01(v.y) * k;
    o.z = leaky_clamp01(v.z) * k;
    o.w = leaky_clamp01(v.w) * k;
    *reinterpret_cast<float4*>(g_awk + idx) = o;
}

__global__ __launch_bounds__(256, 3)
void esl_main_kernel(const float* __restrict__ x,
                     const float* __restrict__ log_tau,
                     float* __restrict__ out) {
    const int lane = threadIdx.x & 31;
    const int warp = threadIdx.x >> 5;

    const int o0 = (blockIdx.x * WARPS + warp) * RB_O;
    const int b0 = blockIdx.y * RB_B;

    const float* __restrict__ xrow = x + (size_t)b0 * IN_;
    const float* __restrict__ arow = g_awk + (size_t)o0 * IN_;

    uint64_t num[RB_B * RB_O];
    uint64_t den[RB_B * RB_O];
#pragma unroll
    for (int t = 0; t < RB_B * RB_O; t++) { num[t] = 0ull; den[t] = 0ull; }

    // 8 logical iterations over i: outer x4 (runtime), inner x2 (compile-time
    // parity u drives the half-poly tile).
#pragma unroll 1
    for (int it = 0; it < 4; it++) {
#pragma unroll
        for (int u = 0; u < 2; u++) {
            const int ic = it * 256 + u * 128 + lane * 4;

            float4 xv[RB_B];
            float4 av[RB_O];
#pragma unroll
            for (int rb = 0; rb < RB_B; rb++)
                xv[rb] = *reinterpret_cast<const float4*>(xrow + rb * IN_ + ic);
#pragma unroll
            for (int ro = 0; ro < RB_O; ro++)
                av[ro] = *reinterpret_cast<const float4*>(arow + ro * IN_ + ic);

            uint64_t xp[RB_B][2], ap[RB_O][2];
#pragma unroll
            for (int rb = 0; rb < RB_B; rb++) {
                xp[rb][0] = pk2(xv[rb].x, xv[rb].y);
                xp[rb][1] = pk2(xv[rb].z, xv[rb].w);
            }
#pragma unroll
            for (int ro = 0; ro < RB_O; ro++) {
                ap[ro][0] = pk2(av[ro].x, av[ro].y);
                ap[ro][1] = pk2(av[ro].z, av[ro].w);
            }

#pragma unroll
            for (int rb = 0; rb < RB_B; rb++) {
#pragma unroll
                for (int ro = 0; ro < RB_O; ro++) {
                    const int t = rb * RB_O + ro;
                    // 2.5 of 8 tiles on the FMA-pipe polynomial path:
                    // tiles 1,3 always; tile 5 on odd sub-iterations.
                    const bool poly = (t == 1) || (t == 3) || (t == 5 && u == 1);
#pragma unroll
                    for (int s = 0; s < 2; s++) {
                        uint64_t a = mul2(xp[rb][s], ap[ro][s]);
                        uint64_t e = poly ? exp2_poly2(a) : exp2_mufu2(a);
                        den[t] = add2(den[t], e);
                        num[t] = fma2(a, e, num[t]);
                    }
                }
            }
        }
    }

    const float inv_k = 1.0f / (expf(log_tau[0]) * LOG2E);

#pragma unroll
    for (int rb = 0; rb < RB_B; rb++) {
#pragma unroll
        for (int ro = 0; ro < RB_O; ro++) {
            const int t = rb * RB_O + ro;
            float n0, n1, d0, d1;
            unpk2(num[t], n0, n1);
            unpk2(den[t], d0, d1);
            float n = n0 + n1;
            float d = d0 + d1;
#pragma unroll
            for (int off = 16; off > 0; off >>= 1) {
                n += __shfl_xor_sync(0xFFFFFFFFu, n, off);
                d += __shfl_xor_sync(0xFFFFFFFFu, d, off);
            }
            if (lane == 0) {
                out[(size_t)(b0 + rb) * OUT_ + (o0 + ro)] = (n / d) * inv_k;
            }
        }
    }
}

extern "C" void kernel_launch(void* const* d_in, const int* in_sizes, int n_in,
                              void* d_out, int out_size) {
    const float* x       = (const float*)d_in[0];  // (256, 1024)
    const float* weight  = (const float*)d_in[1];  // (1024, 1024)
    const float* log_tau = (const float*)d_in[2];  // scalar
    float* out           = (float*)d_out;          // (256, 1024)

    prep_awk_kernel<<<(OUT_ * IN_) / (256 * 4), 256>>>(weight, log_tau);

    dim3 grid(OUT_ / (WARPS * RB_O), B_ / RB_B);
    esl_main_kernel<<<grid, 256>>>(x, log_tau, out);
}